// round 2
// baseline (speedup 1.0000x reference)
#include <cuda_runtime.h>

#define BATCH 65536
#define DIM   512
#define KC    1024
#define NCLS  100
#define GAMMA 0.99f
#define EPSV  1e-5f

#define DK (DIM * KC)      // 524288
#define KCC (KC * NCLS)    // 102400

// ---- scratch (device globals, no allocs) ----
__device__ float g_wsq[KC];
__device__ float g_counts[KC];
__device__ float g_esum[KC * DIM];   // [K][D] layout for coalesced scatter
__device__ float g_bhist[KC * NCLS];
__device__ int   g_argmin[BATCH];
__device__ float g_n;

// ---------------------------------------------------------------
// zero scratch
// ---------------------------------------------------------------
__global__ void zero_kernel() {
    int total = KC + KC * DIM + KC * NCLS;
    for (int i = blockIdx.x * blockDim.x + threadIdx.x; i < total;
         i += gridDim.x * blockDim.x) {
        if (i < KC) g_counts[i] = 0.0f;
        else if (i < KC + KC * DIM) g_esum[i - KC] = 0.0f;
        else g_bhist[i - KC - KC * DIM] = 0.0f;
    }
}

// ---------------------------------------------------------------
// w_sq[k] = sum_d W[d,k]^2   (coalesced across k)
// ---------------------------------------------------------------
__global__ void wsq_kernel(const float* __restrict__ W) {
    int k = blockIdx.x * blockDim.x + threadIdx.x;
    if (k >= KC) return;
    float a = 0.0f;
    #pragma unroll 8
    for (int d = 0; d < DIM; d++) {
        float w = W[d * KC + k];
        a += w * w;
    }
    g_wsq[k] = a;
}

// ---------------------------------------------------------------
// Fused GEMM + argmin.
// Per block: BM=128 rows, loops over all K in BN=64 tiles, D in BD=16 chunks.
// Per thread: 8x4 microtile -> 32 FFMA : 3 LDS.128 per d-step.
// score = w_sq[k] - 2*dot(x,w)  (monotone-equivalent to the reference dist)
// ---------------------------------------------------------------
#define BM 128
#define BN 64
#define BD 16

__global__ __launch_bounds__(256, 2)
void argmin_kernel(const float* __restrict__ X, const float* __restrict__ W,
                   float* __restrict__ out_am) {
    __shared__ float Xs[BD][BM];         // 8 KB
    __shared__ float Ws[BD][BN];         // 4 KB
    __shared__ float red_v[BM][16];      // 8 KB
    __shared__ int   red_i[BM][16];      // 8 KB

    int tid = threadIdx.x;
    int tr = tid >> 4;          // 0..15 -> rows tr*8 .. tr*8+7
    int tc = tid & 15;          // 0..15 -> cols tc*4 .. tc*4+3
    int row0 = blockIdx.x * BM;

    float bestv[8];
    int   besti[8];
    #pragma unroll
    for (int i = 0; i < 8; i++) { bestv[i] = 3.4e38f; besti[i] = 0; }

    for (int n0 = 0; n0 < KC; n0 += BN) {
        float acc[8][4] = {};
        for (int d0 = 0; d0 < DIM; d0 += BD) {
            // load X tile (128 x 16) transposed into Xs: 2 float4 per thread
            {
                int r    = tid >> 1;           // 0..127
                int c4   = (tid & 1) * 8;      // 0 or 8
                const float* xp = &X[(size_t)(row0 + r) * DIM + d0 + c4];
                float4 v0 = *reinterpret_cast<const float4*>(xp);
                float4 v1 = *reinterpret_cast<const float4*>(xp + 4);
                Xs[c4 + 0][r] = v0.x; Xs[c4 + 1][r] = v0.y;
                Xs[c4 + 2][r] = v0.z; Xs[c4 + 3][r] = v0.w;
                Xs[c4 + 4][r] = v1.x; Xs[c4 + 5][r] = v1.y;
                Xs[c4 + 6][r] = v1.z; Xs[c4 + 7][r] = v1.w;
            }
            // load W tile (16 x 64): 1 float4 per thread
            {
                int dd = tid >> 4;           // 0..15
                int c4 = (tid & 15) * 4;     // 0..60
                float4 v = *reinterpret_cast<const float4*>(
                    &W[(size_t)(d0 + dd) * KC + n0 + c4]);
                *reinterpret_cast<float4*>(&Ws[dd][c4]) = v;
            }
            __syncthreads();
            #pragma unroll
            for (int d = 0; d < BD; d++) {
                float4 xv0 = *reinterpret_cast<const float4*>(&Xs[d][tr * 8]);
                float4 xv1 = *reinterpret_cast<const float4*>(&Xs[d][tr * 8 + 4]);
                float4 wv  = *reinterpret_cast<const float4*>(&Ws[d][tc * 4]);
                float xr[8] = {xv0.x, xv0.y, xv0.z, xv0.w,
                               xv1.x, xv1.y, xv1.z, xv1.w};
                float wr[4] = {wv.x, wv.y, wv.z, wv.w};
                #pragma unroll
                for (int i = 0; i < 8; i++)
                    #pragma unroll
                    for (int j = 0; j < 4; j++)
                        acc[i][j] += xr[i] * wr[j];
            }
            __syncthreads();
        }
        // score + running min (k scanned ascending -> strict < keeps lowest idx)
        #pragma unroll
        for (int j = 0; j < 4; j++) {
            int k = n0 + tc * 4 + j;
            float wsq = g_wsq[k];
            #pragma unroll
            for (int i = 0; i < 8; i++) {
                float s = wsq - 2.0f * acc[i][j];
                if (s < bestv[i]) { bestv[i] = s; besti[i] = k; }
            }
        }
    }

    // cross-thread reduce over the 16 column-threads of each row
    #pragma unroll
    for (int i = 0; i < 8; i++) {
        red_v[tr * 8 + i][tc] = bestv[i];
        red_i[tr * 8 + i][tc] = besti[i];
    }
    __syncthreads();
    if (tid < BM) {
        float bv = red_v[tid][0];
        int   bi = red_i[tid][0];
        #pragma unroll
        for (int t = 1; t < 16; t++) {
            float v = red_v[tid][t];
            int  ii = red_i[tid][t];
            if (v < bv || (v == bv && ii < bi)) { bv = v; bi = ii; }
        }
        int b = row0 + tid;
        g_argmin[b] = bi;
        out_am[b] = (float)bi;
    }
}

// ---------------------------------------------------------------
// Scatter: counts, class histogram, embed_sum (coalesced atomics, [K][D])
// ---------------------------------------------------------------
__global__ void scatter_kernel(const float* __restrict__ X,
                               const int* __restrict__ keys) {
    int b = blockIdx.x;
    int k = g_argmin[b];
    int t = threadIdx.x;   // 128 threads
    if (t == 0) {
        atomicAdd(&g_counts[k], 1.0f);
        atomicAdd(&g_bhist[k * NCLS + keys[b]], 1.0f);
    }
    const float* xr = X + (size_t)b * DIM;
    float* es = g_esum + (size_t)k * DIM;
    #pragma unroll 4
    for (int d = t; d < DIM; d += 128)
        atomicAdd(&es[d], xr[d]);
}

// ---------------------------------------------------------------
// finalize cluster_size + n
// ---------------------------------------------------------------
__global__ void fincs_kernel(const float* __restrict__ cs,
                             float* __restrict__ out_cs) {
    __shared__ float sred[KC];
    int k = threadIdx.x;
    float c = g_counts[k];
    if (c == 0.0f) c = 1.0f;
    float ncs = cs[k] * GAMMA + (1.0f - GAMMA) * c;
    out_cs[k] = ncs;
    sred[k] = ncs;
    __syncthreads();
    for (int s = KC / 2; s > 0; s >>= 1) {
        if (k < s) sred[k] += sred[k + s];
        __syncthreads();
    }
    if (k == 0) g_n = sred[0];
}

// ---------------------------------------------------------------
// finalize weight + embed_avg
// ---------------------------------------------------------------
__global__ void finw_kernel(const float* __restrict__ ea,
                            const float* __restrict__ out_cs,
                            float* __restrict__ out_w,
                            float* __restrict__ out_ea) {
    int i = blockIdx.x * blockDim.x + threadIdx.x;
    if (i >= DK) return;
    int k = i & (KC - 1);
    int d = i >> 10;
    float e = ea[i] * GAMMA + (1.0f - GAMMA) * g_esum[(size_t)k * DIM + d];
    out_ea[i] = e;
    float n = g_n;
    float csn = (out_cs[k] + EPSV) / (n + KC * EPSV) * n;
    out_w[i] = e / csn;
}

// ---------------------------------------------------------------
// finalize hist
// ---------------------------------------------------------------
__global__ void finh_kernel(const float* __restrict__ hist,
                            float* __restrict__ out_h) {
    int i = blockIdx.x * blockDim.x + threadIdx.x;
    if (i >= KCC) return;
    out_h[i] = hist[i] * GAMMA + (1.0f - GAMMA) * g_bhist[i];
}

// ---------------------------------------------------------------
extern "C" void kernel_launch(void* const* d_in, const int* in_sizes, int n_in,
                              void* d_out, int out_size) {
    const float* X    = (const float*)d_in[0];  // [B,D]
    const int*   keys = (const int*)  d_in[1];  // [B]
    const float* W    = (const float*)d_in[2];  // [D,K]
    const float* cs   = (const float*)d_in[3];  // [K]
    const float* ea   = (const float*)d_in[4];  // [D,K]
    const float* hist = (const float*)d_in[5];  // [K,C]

    float* out    = (float*)d_out;
    float* out_w  = out;                        // D*K
    float* out_cs = out + DK;                   // K
    float* out_ea = out + DK + KC;              // D*K
    float* out_h  = out + DK + KC + DK;         // K*C
    float* out_am = out + DK + KC + DK + KCC;   // B

    int total_zero = KC + KC * DIM + KC * NCLS;
    zero_kernel<<<(total_zero + 255) / 256, 256>>>();
    wsq_kernel<<<(KC + 255) / 256, 256>>>(W);
    argmin_kernel<<<BATCH / BM, 256>>>(X, W, out_am);
    scatter_kernel<<<BATCH, 128>>>(X, keys);
    fincs_kernel<<<1, KC>>>(cs, out_cs);
    finw_kernel<<<(DK + 255) / 256, 256>>>(ea, out_cs, out_w, out_ea);
    finh_kernel<<<(KCC + 255) / 256, 256>>>(hist, out_h);
}

// round 4
// speedup vs baseline: 3.4928x; 3.4928x over previous
#include <cuda_runtime.h>
#include <cuda_bf16.h>
#include <cstdint>
#include <float.h>

#define BATCH 65536
#define DIM   512
#define KC    1024
#define NCLS  100
#define GAMMA 0.99f
#define EPSV  1e-5f

#define DK (DIM * KC)      // 524288
#define KCC (KC * NCLS)    // 102400

// ---------------- scratch (device globals) ----------------
__device__ float          g_wsq[KC];
__device__ float          g_counts[KC];
__device__ float          g_esum[KC * DIM];     // [K][D]
__device__ float          g_bhist[KC * NCLS];
__device__ int            g_argmin[BATCH];
__device__ float          g_n;
__device__ __nv_bfloat16  g_wbf[DIM * KC];      // bf16 copy of W, [D][K]
__device__ float          g_wt32[KC * DIM];     // W^T fp32 [K][D] (rescue)
__device__ int            g_rescue_cnt;
__device__ int            g_r_row[BATCH];
__device__ int            g_r_k[BATCH * 4];

// ---------------- PTX helpers (sm_100-base safe) ----------------
__device__ __forceinline__ uint32_t smem_u32(const void* p) {
    uint32_t a;
    asm("{ .reg .u64 t; cvta.to.shared.u64 t, %1; cvt.u32.u64 %0, t; }"
        : "=r"(a) : "l"(p));
    return a;
}
__device__ __forceinline__ void ldsm_x4(uint32_t* r, uint32_t addr) {
    asm volatile("ldmatrix.sync.aligned.m8n8.x4.shared.b16 {%0,%1,%2,%3}, [%4];"
                 : "=r"(r[0]), "=r"(r[1]), "=r"(r[2]), "=r"(r[3]) : "r"(addr));
}
__device__ __forceinline__ void ldsm_x4_t(uint32_t* r, uint32_t addr) {
    asm volatile("ldmatrix.sync.aligned.m8n8.x4.trans.shared.b16 {%0,%1,%2,%3}, [%4];"
                 : "=r"(r[0]), "=r"(r[1]), "=r"(r[2]), "=r"(r[3]) : "r"(addr));
}
__device__ __forceinline__ void mma16816(float* c, const uint32_t* a,
                                         uint32_t b0, uint32_t b1) {
    asm volatile("mma.sync.aligned.m16n8k16.row.col.f32.bf16.bf16.f32 "
                 "{%0,%1,%2,%3}, {%4,%5,%6,%7}, {%8,%9}, {%0,%1,%2,%3};"
                 : "+f"(c[0]), "+f"(c[1]), "+f"(c[2]), "+f"(c[3])
                 : "r"(a[0]), "r"(a[1]), "r"(a[2]), "r"(a[3]), "r"(b0), "r"(b1));
}
__device__ __forceinline__ uint32_t bf2u(float lo, float hi) {
    __nv_bfloat162 p = __floats2bfloat162_rn(lo, hi);
    return *reinterpret_cast<uint32_t*>(&p);
}

// ---------------------------------------------------------------
__global__ void zero_kernel() {
    int total = KC + KC * DIM + KC * NCLS;
    for (int i = blockIdx.x * blockDim.x + threadIdx.x; i < total;
         i += gridDim.x * blockDim.x) {
        if (i < KC) g_counts[i] = 0.0f;
        else if (i < KC + KC * DIM) g_esum[i - KC] = 0.0f;
        else g_bhist[i - KC - KC * DIM] = 0.0f;
    }
    if (blockIdx.x == 0 && threadIdx.x == 0) g_rescue_cnt = 0;
}

// w_sq[k] = sum_d W[d,k]^2 in fp32 (coalesced across k)
__global__ void wsq_kernel(const float* __restrict__ W) {
    int k = blockIdx.x * blockDim.x + threadIdx.x;
    if (k >= KC) return;
    float a = 0.0f;
    #pragma unroll 8
    for (int d = 0; d < DIM; d++) {
        float w = W[d * KC + k];
        a += w * w;
    }
    g_wsq[k] = a;
}

// Transpose W [D][K] -> W^T fp32 [K][D] (rescue) + write bf16 copy [D][K]
__global__ void wt_kernel(const float* __restrict__ W) {
    __shared__ float tile[32][33];
    int k0 = blockIdx.x * 32, d0 = blockIdx.y * 32;
    int tx = threadIdx.x, ty = threadIdx.y;   // (32, 8)
    #pragma unroll
    for (int j = 0; j < 4; j++) {
        size_t gi = (size_t)(d0 + ty + 8 * j) * KC + k0 + tx;
        float v = W[gi];
        tile[ty + 8 * j][tx] = v;
        g_wbf[gi] = __float2bfloat16_rn(v);
    }
    __syncthreads();
    #pragma unroll
    for (int j = 0; j < 4; j++)
        g_wt32[(size_t)(k0 + ty + 8 * j) * DIM + d0 + tx] = tile[tx][ty + 8 * j];
}

// ---------------------------------------------------------------
// mma.sync bf16 GEMM + top-2/top-4 argmin.
// CTA: 256 threads (8 warps, 4m x 2n), 128 batch rows.
// X tile (128x512 bf16) resident in smem; B tile = W rows d0..d0+63,
// cols n0..n0+127, stored [k][n] (native W layout), single buffer with
// register prefetch. XOR-swizzled 16B units -> conflict-free ldmatrix.
// ---------------------------------------------------------------
#define SA_OFF   0           // 131072 bytes: A [128][512] bf16, row 1024B
#define SB_OFF   131072      // 16384 bytes:  B [64][128] bf16, row 256B
#define WSQ_OFF  147456      // 4096 bytes
#define RED_OFF  151552      // 16384 bytes: red[128][8] float4
#define SM_TOTAL 167936
#define RESCUE_T 2.0f

__global__ __launch_bounds__(256, 1)
void argmin_mma(const float* __restrict__ X, float* __restrict__ out_am) {
    extern __shared__ unsigned char sm[];
    uint32_t smb = smem_u32(sm);
    float*  s_wsq = (float*)(sm + WSQ_OFF);
    float4* red   = (float4*)(sm + RED_OFF);

    int tid  = threadIdx.x;
    int lane = tid & 31;
    int wid  = tid >> 5;
    int wm   = wid >> 1;        // 0..3  -> rows wm*32..+32
    int wn   = wid & 1;         // 0..1  -> cols wn*64..+64
    int row0 = blockIdx.x * 128;

    // ---- fill wsq smem ----
    #pragma unroll
    for (int i = tid; i < KC; i += 256) s_wsq[i] = g_wsq[i];

    // ---- load X tile -> bf16 swizzled smem ----
    #pragma unroll
    for (int it = 0; it < 32; it++) {
        int ul = it * 256 + tid;        // 0..8191 16B units
        int r = ul >> 6, u = ul & 63;
        const float4* xp = reinterpret_cast<const float4*>(
            &X[(size_t)(row0 + r) * DIM + u * 8]);
        float4 f0 = xp[0], f1 = xp[1];
        uint4 q;
        q.x = bf2u(f0.x, f0.y); q.y = bf2u(f0.z, f0.w);
        q.z = bf2u(f1.x, f1.y); q.w = bf2u(f1.z, f1.w);
        *reinterpret_cast<uint4*>(sm + SA_OFF + r * 1024 + ((u ^ (r & 7)) * 16)) = q;
    }

    // per-thread top-2 for 4 row-slots (i in 0..1, half in 0..1)
    float tv1[4], tv2[4];
    int   tk1[4], tk2[4];
    #pragma unroll
    for (int s = 0; s < 4; s++) { tv1[s] = FLT_MAX; tv2[s] = FLT_MAX; tk1[s] = KC; tk2[s] = KC; }

    // prefetch chunk 0
    uint4 bpre[4];
    {
        #pragma unroll
        for (int t = 0; t < 4; t++) {
            int ul = t * 256 + tid;
            int kr = ul >> 4, u = ul & 15;
            bpre[t] = *reinterpret_cast<const uint4*>(
                &g_wbf[(size_t)kr * KC + u * 8]);
        }
    }

    int mrow = wm * 32 + (lane & 15);
    int hi   = lane >> 4;
    int mx   = mrow & 7;
    int kl   = lane & 15;
    int kx   = kl & 7;

    for (int nc = 0; nc < 8; nc++) {
        float acc[2][8][4];
        #pragma unroll
        for (int i = 0; i < 2; i++)
            #pragma unroll
            for (int j = 0; j < 8; j++)
                #pragma unroll
                for (int c = 0; c < 4; c++) acc[i][j][c] = 0.0f;

        for (int dc = 0; dc < 8; dc++) {
            int c = nc * 8 + dc;
            __syncthreads();                  // buffer free (prev compute done)
            #pragma unroll
            for (int t = 0; t < 4; t++) {
                int ul = t * 256 + tid;
                int kr = ul >> 4, u = ul & 15;
                *reinterpret_cast<uint4*>(
                    sm + SB_OFF + kr * 256 + ((u ^ (kr & 7)) * 16)) = bpre[t];
            }
            __syncthreads();                  // tile visible
            if (c + 1 < 64) {                 // prefetch next (hidden under MMAs)
                int d0n = ((c + 1) & 7) * 64, n0n = ((c + 1) >> 3) * 128;
                #pragma unroll
                for (int t = 0; t < 4; t++) {
                    int ul = t * 256 + tid;
                    int kr = ul >> 4, u = ul & 15;
                    bpre[t] = *reinterpret_cast<const uint4*>(
                        &g_wbf[(size_t)(d0n + kr) * KC + n0n + u * 8]);
                }
            }
            // ---- 4 k-steps of ldmatrix + mma ----
            #pragma unroll
            for (int ks = 0; ks < 4; ks++) {
                uint32_t a[2][4];
                #pragma unroll
                for (int i = 0; i < 2; i++)
                    ldsm_x4(a[i], smb + SA_OFF + (mrow + i * 16) * 1024 +
                                  (((dc * 8 + ks * 2 + hi) ^ mx) * 16));
                uint32_t bfr[4][4];
                #pragma unroll
                for (int jj = 0; jj < 4; jj++)
                    ldsm_x4_t(bfr[jj], smb + SB_OFF + (ks * 16 + kl) * 256 +
                                       (((wn * 8 + jj * 2 + hi) ^ kx) * 16));
                #pragma unroll
                for (int i = 0; i < 2; i++)
                    #pragma unroll
                    for (int jj = 0; jj < 4; jj++) {
                        mma16816(acc[i][jj * 2],     a[i], bfr[jj][0], bfr[jj][1]);
                        mma16816(acc[i][jj * 2 + 1], a[i], bfr[jj][2], bfr[jj][3]);
                    }
            }
        }

        // ---- epilogue: scores + running top-2 per row-slot ----
        int kbase = nc * 128 + wn * 64 + (lane & 3) * 2;
        float wv[16];
        #pragma unroll
        for (int j = 0; j < 8; j++) {
            wv[2 * j]     = s_wsq[kbase + j * 8];
            wv[2 * j + 1] = s_wsq[kbase + j * 8 + 1];
        }
        #pragma unroll
        for (int i = 0; i < 2; i++)
            #pragma unroll
            for (int h = 0; h < 2; h++) {
                int slot = i * 2 + h;
                #pragma unroll
                for (int j = 0; j < 8; j++) {
                    int kg = kbase + j * 8;
                    float s0 = fmaf(-2.0f, acc[i][j][h * 2 + 0], wv[2 * j]);
                    float s1 = fmaf(-2.0f, acc[i][j][h * 2 + 1], wv[2 * j + 1]);
                    if (s0 < tv1[slot])      { tv2[slot] = tv1[slot]; tk2[slot] = tk1[slot]; tv1[slot] = s0; tk1[slot] = kg; }
                    else if (s0 < tv2[slot]) { tv2[slot] = s0; tk2[slot] = kg; }
                    if (s1 < tv1[slot])      { tv2[slot] = tv1[slot]; tk2[slot] = tk1[slot]; tv1[slot] = s1; tk1[slot] = kg + 1; }
                    else if (s1 < tv2[slot]) { tv2[slot] = s1; tk2[slot] = kg + 1; }
                }
            }
    }

    // ---- write per-thread top-2 to merge smem ----
    __syncthreads();   // done with B buffer / safe to write red region
    int ci = wn * 4 + (lane & 3);
    #pragma unroll
    for (int i = 0; i < 2; i++)
        #pragma unroll
        for (int h = 0; h < 2; h++) {
            int slot = i * 2 + h;
            int r = wm * 32 + i * 16 + h * 8 + (lane >> 2);
            float4 e;
            e.x = tv1[slot]; e.y = __int_as_float(tk1[slot]);
            e.z = tv2[slot]; e.w = __int_as_float(tk2[slot]);
            red[r * 8 + ci] = e;
        }
    __syncthreads();

    // ---- per-row merge: top-4 of 16 candidates, lexicographic (v, k) ----
    if (tid < 128) {
        float bv[4] = {FLT_MAX, FLT_MAX, FLT_MAX, FLT_MAX};
        int   bk[4] = {KC, KC, KC, KC};
        #pragma unroll
        for (int c = 0; c < 8; c++) {
            float4 e = red[tid * 8 + c];
            float cv[2] = {e.x, e.z};
            int   ck[2] = {__float_as_int(e.y), __float_as_int(e.w)};
            #pragma unroll
            for (int w = 0; w < 2; w++) {
                float v = cv[w]; int k = ck[w];
                if (v < bv[3] || (v == bv[3] && k < bk[3])) {
                    bv[3] = v; bk[3] = k;
                    if (bv[3] < bv[2] || (bv[3] == bv[2] && bk[3] < bk[2])) {
                        float t = bv[2]; bv[2] = bv[3]; bv[3] = t;
                        int ti = bk[2]; bk[2] = bk[3]; bk[3] = ti;
                    }
                    if (bv[2] < bv[1] || (bv[2] == bv[1] && bk[2] < bk[1])) {
                        float t = bv[1]; bv[1] = bv[2]; bv[2] = t;
                        int ti = bk[1]; bk[1] = bk[2]; bk[2] = ti;
                    }
                    if (bv[1] < bv[0] || (bv[1] == bv[0] && bk[1] < bk[0])) {
                        float t = bv[0]; bv[0] = bv[1]; bv[1] = t;
                        int ti = bk[0]; bk[0] = bk[1]; bk[1] = ti;
                    }
                }
            }
        }
        int b = row0 + tid;
        if (bv[1] - bv[0] > RESCUE_T) {
            g_argmin[b] = bk[0];
            out_am[b] = (float)bk[0];
        } else {
            int e = atomicAdd(&g_rescue_cnt, 1);
            g_r_row[e] = b;
            #pragma unroll
            for (int w = 0; w < 4; w++) g_r_k[e * 4 + w] = bk[w];
        }
    }
}

// ---------------------------------------------------------------
// Exact fp32 rescue: top-4 candidates per flagged row, one warp each.
// ---------------------------------------------------------------
__global__ void rescue_kernel(const float* __restrict__ X,
                              float* __restrict__ out_am) {
    int lane = threadIdx.x & 31;
    int warpGlobal = (blockIdx.x * blockDim.x + threadIdx.x) >> 5;
    int nWarps = (gridDim.x * blockDim.x) >> 5;
    int cnt = g_rescue_cnt;
    for (int e = warpGlobal; e < cnt; e += nWarps) {
        int b = g_r_row[e];
        int kk[4];
        #pragma unroll
        for (int w = 0; w < 4; w++) kk[w] = g_r_k[e * 4 + w];
        const float* xr = X + (size_t)b * DIM;
        float dot[4] = {0.0f, 0.0f, 0.0f, 0.0f};
        #pragma unroll 4
        for (int d = lane; d < DIM; d += 32) {
            float x = xr[d];
            #pragma unroll
            for (int w = 0; w < 4; w++)
                if (kk[w] < KC)
                    dot[w] += x * g_wt32[(size_t)kk[w] * DIM + d];
        }
        #pragma unroll
        for (int off = 16; off > 0; off >>= 1)
            #pragma unroll
            for (int w = 0; w < 4; w++)
                dot[w] += __shfl_xor_sync(0xffffffff, dot[w], off);
        if (lane == 0) {
            float bv = FLT_MAX; int bi = KC;
            #pragma unroll
            for (int w = 0; w < 4; w++) {
                if (kk[w] >= KC) continue;
                float s = g_wsq[kk[w]] - 2.0f * dot[w];
                if (s < bv || (s == bv && kk[w] < bi)) { bv = s; bi = kk[w]; }
            }
            g_argmin[b] = bi;
            out_am[b] = (float)bi;
        }
    }
}

// ---------------------------------------------------------------
__global__ void scatter_kernel(const float* __restrict__ X,
                               const int* __restrict__ keys) {
    int b = blockIdx.x;
    int k = g_argmin[b];
    int t = threadIdx.x;   // 128 threads
    if (t == 0) {
        atomicAdd(&g_counts[k], 1.0f);
        atomicAdd(&g_bhist[k * NCLS + keys[b]], 1.0f);
    }
    const float* xr = X + (size_t)b * DIM;
    float* es = g_esum + (size_t)k * DIM;
    #pragma unroll 4
    for (int d = t; d < DIM; d += 128)
        atomicAdd(&es[d], xr[d]);
}

__global__ void fincs_kernel(const float* __restrict__ cs,
                             float* __restrict__ out_cs) {
    __shared__ float sred[KC];
    int k = threadIdx.x;
    float c = g_counts[k];
    if (c == 0.0f) c = 1.0f;
    float ncs = cs[k] * GAMMA + (1.0f - GAMMA) * c;
    out_cs[k] = ncs;
    sred[k] = ncs;
    __syncthreads();
    for (int s = KC / 2; s > 0; s >>= 1) {
        if (k < s) sred[k] += sred[k + s];
        __syncthreads();
    }
    if (k == 0) g_n = sred[0];
}

__global__ void finw_kernel(const float* __restrict__ ea,
                            const float* __restrict__ out_cs,
                            float* __restrict__ out_w,
                            float* __restrict__ out_ea) {
    int i = blockIdx.x * blockDim.x + threadIdx.x;
    if (i >= DK) return;
    int k = i & (KC - 1);
    int d = i >> 10;
    float e = ea[i] * GAMMA + (1.0f - GAMMA) * g_esum[(size_t)k * DIM + d];
    out_ea[i] = e;
    float n = g_n;
    float csn = (out_cs[k] + EPSV) / (n + KC * EPSV) * n;
    out_w[i] = e / csn;
}

__global__ void finh_kernel(const float* __restrict__ hist,
                            float* __restrict__ out_h) {
    int i = blockIdx.x * blockDim.x + threadIdx.x;
    if (i >= KCC) return;
    out_h[i] = hist[i] * GAMMA + (1.0f - GAMMA) * g_bhist[i];
}

// ---------------------------------------------------------------
extern "C" void kernel_launch(void* const* d_in, const int* in_sizes, int n_in,
                              void* d_out, int out_size) {
    const float* X    = (const float*)d_in[0];  // [B,D]
    const int*   keys = (const int*)  d_in[1];  // [B]
    const float* W    = (const float*)d_in[2];  // [D,K]
    const float* cs   = (const float*)d_in[3];  // [K]
    const float* ea   = (const float*)d_in[4];  // [D,K]
    const float* hist = (const float*)d_in[5];  // [K,C]

    float* out    = (float*)d_out;
    float* out_w  = out;                        // D*K
    float* out_cs = out + DK;                   // K
    float* out_ea = out + DK + KC;              // D*K
    float* out_h  = out + DK + KC + DK;         // K*C
    float* out_am = out + DK + KC + DK + KCC;   // B

    cudaFuncSetAttribute(argmin_mma, cudaFuncAttributeMaxDynamicSharedMemorySize,
                         SM_TOTAL);

    int total_zero = KC + KC * DIM + KC * NCLS;
    zero_kernel<<<(total_zero + 255) / 256, 256>>>();
    wsq_kernel<<<(KC + 255) / 256, 256>>>(W);
    wt_kernel<<<dim3(KC / 32, DIM / 32), dim3(32, 8)>>>(W);
    argmin_mma<<<BATCH / 128, 256, SM_TOTAL>>>(X, out_am);
    rescue_kernel<<<128, 128>>>(X, out_am);
    scatter_kernel<<<BATCH, 128>>>(X, keys);
    fincs_kernel<<<1, KC>>>(cs, out_cs);
    finw_kernel<<<(DK + 255) / 256, 256>>>(ea, out_cs, out_w, out_ea);
    finh_kernel<<<(KCC + 255) / 256, 256>>>(hist, out_h);
}